// round 7
// baseline (speedup 1.0000x reference)
#include <cuda_runtime.h>
#include <cstdint>

// QuantizedEmbedding R7: persistent-style pipeline.
// grid=1024 CTAs x 16 contiguous tokens. Prefetch: indices 2 ahead, weight
// rows 1 ahead (breaks the index->row pointer chase). Warp-autonomous 2KB
// cp.async.bulk stores, double-buffered smem, wait_group 1. 100% smem carveout.

static constexpr int PACKED   = 2048;    // packed int32 per row
static constexpr int NGROUPS  = 128;
static constexpr int DIM      = 4096;
static constexpr int THREADS  = 256;     // thread t: packed [t*8, t*8+8) -> group t>>1
static constexpr int TOKS     = 16;      // tokens per CTA
static constexpr int WARPS    = THREADS / 32;
static constexpr int SLICE_F  = DIM / WARPS;           // 512 floats = 2KB per warp slice
static constexpr int SLICE_B  = SLICE_F * 4;           // 2048 bytes
static constexpr int SMEM_BYTES = WARPS * 2 * SLICE_B; // 32KB

__device__ __forceinline__ float4 dq2(int a, int b, float s) {
    float4 r;
    r.x = (float)(a / 16 - 8) * s;       // trunc-toward-zero high nibble
    r.y = (float)((a & 15) - 8) * s;     // nonneg mod-16 low nibble
    r.z = (float)(b / 16 - 8) * s;
    r.w = (float)((b & 15) - 8) * s;
    return r;
}

__global__ void __launch_bounds__(THREADS, 7)
qemb_kernel(const int* __restrict__ indices,
            const int* __restrict__ weight,
            const float* __restrict__ scales,
            float* __restrict__ out,
            int n_tokens)
{
    extern __shared__ float4 buf[];   // [WARPS][2][SLICE_F/4]
    int t    = threadIdx.x;
    int warp = t >> 5;
    int lane = t & 31;

    long base = (long)blockIdx.x * TOKS;
    int cnt = n_tokens - (int)base;
    if (cnt <= 0) return;
    if (cnt > TOKS) cnt = TOKS;

    float4* wbuf = buf + (size_t)warp * 2 * (SLICE_F / 4);

    // ---- prologue: token 0 rows + token 1 index ----
    int idx0 = __ldg(indices + base);
    const int4* wr = reinterpret_cast<const int4*>(weight + (long)idx0 * PACKED) + t * 2;
    int4 w0 = __ldg(wr);
    int4 w1 = __ldg(wr + 1);
    float s = __ldg(scales + (long)idx0 * NGROUPS + (t >> 1));
    int idxA = __ldg(indices + base + ((cnt > 1) ? 1 : 0));   // index of token 1 (clamped)

    for (int i = 0; i < cnt; i++) {
        // prefetch index of token i+2 (fully independent)
        int idx_n2 = idxA;
        if (i + 2 < cnt) idx_n2 = __ldg(indices + base + i + 2);

        // prefetch rows of token i+1 using idxA (loaded a full iteration ago)
        int4 n0, n1; float ns;
        if (i + 1 < cnt) {
            const int4* wr2 =
                reinterpret_cast<const int4*>(weight + (long)idxA * PACKED) + t * 2;
            n0 = __ldg(wr2);
            n1 = __ldg(wr2 + 1);
            ns = __ldg(scales + (long)idxA * NGROUPS + (t >> 1));
        }

        // buffer (i&1) reuse guard: its bulk store was committed at iter i-2
        if (i >= 2 && lane == 0)
            asm volatile("cp.async.bulk.wait_group %0;" :: "n"(1) : "memory");
        __syncwarp();

        // dequant straight into smem (lane writes 4 consecutive float4 = 64B)
        float4* b = wbuf + (size_t)(i & 1) * (SLICE_F / 4) + lane * 4;
        b[0] = dq2(w0.x, w0.y, s);
        b[1] = dq2(w0.z, w0.w, s);
        b[2] = dq2(w1.x, w1.y, s);
        b[3] = dq2(w1.z, w1.w, s);

        asm volatile("fence.proxy.async.shared::cta;" ::: "memory");
        __syncwarp();

        if (lane == 0) {
            uint32_t saddr = (uint32_t)__cvta_generic_to_shared(
                wbuf + (size_t)(i & 1) * (SLICE_F / 4));
            void* g = (void*)(out + (base + i) * DIM + warp * SLICE_F);
            asm volatile("cp.async.bulk.global.shared::cta.bulk_group [%0], [%1], %2;"
                         :: "l"(g), "r"(saddr), "n"(SLICE_B) : "memory");
            asm volatile("cp.async.bulk.commit_group;" ::: "memory");
        }

        w0 = n0; w1 = n1; s = ns; idxA = idx_n2;
    }

    if (lane == 0)
        asm volatile("cp.async.bulk.wait_group 0;" ::: "memory");
}

extern "C" void kernel_launch(void* const* d_in, const int* in_sizes, int n_in,
                              void* d_out, int out_size)
{
    const int*   indices = (const int*)d_in[0];
    const int*   weight  = (const int*)d_in[1];
    const float* scales  = (const float*)d_in[2];
    float*       out     = (float*)d_out;

    int n_tokens = in_sizes[0];  // 16384

    cudaFuncSetAttribute(qemb_kernel,
                         cudaFuncAttributeMaxDynamicSharedMemorySize, SMEM_BYTES);
    // ask for max smem carveout so 7 x 32KB CTAs fit per SM
    cudaFuncSetAttribute(qemb_kernel,
                         cudaFuncAttributePreferredSharedMemoryCarveout, 100);

    int grid = (n_tokens + TOKS - 1) / TOKS;  // 1024
    qemb_kernel<<<grid, THREADS, SMEM_BYTES>>>(indices, weight, scales, out, n_tokens);
}

// round 8
// speedup vs baseline: 1.1895x; 1.1895x over previous
#include <cuda_runtime.h>
#include <cstdint>

// QuantizedEmbedding R8: half-row CTAs to decouple smem from occupancy.
// Each CTA: 128 threads (4 warps), handles the half-row (2048 floats) of 4
// consecutive tokens. smem = 2 x 8KB = 16KB -> up to 14 CTAs/SM (87.5% occ)
// with __launch_bounds__(128,14). Warp-autonomous 2KB cp.async.bulk stores,
// double-buffered, weight rows prefetched 1 token ahead. grid = 8192.

static constexpr int PACKED   = 2048;    // packed int32 per row
static constexpr int NGROUPS  = 128;
static constexpr int DIM      = 4096;
static constexpr int THREADS  = 128;
static constexpr int TOKS     = 4;       // tokens per CTA
static constexpr int HALF_F   = DIM / 2;              // 2048 floats per half-row
static constexpr int HALF_P   = PACKED / 2;           // 1024 packed per half-row
static constexpr int WARPS    = THREADS / 32;         // 4
static constexpr int SLICE_F  = HALF_F / WARPS;       // 512 floats = 2KB per warp
static constexpr int SLICE_B  = SLICE_F * 4;          // 2048 B
static constexpr int SMEM_BYTES = WARPS * 2 * SLICE_B; // 16KB

__device__ __forceinline__ float4 dq2(int a, int b, float s) {
    float4 r;
    r.x = (float)(a / 16 - 8) * s;       // trunc-toward-zero high nibble
    r.y = (float)((a & 15) - 8) * s;     // nonneg mod-16 low nibble
    r.z = (float)(b / 16 - 8) * s;
    r.w = (float)((b & 15) - 8) * s;
    return r;
}

__global__ void __launch_bounds__(THREADS, 14)
qemb_kernel(const int* __restrict__ indices,
            const int* __restrict__ weight,
            const float* __restrict__ scales,
            float* __restrict__ out,
            int n_tokens)
{
    extern __shared__ float4 buf[];   // [WARPS][2][SLICE_F/4]
    int t    = threadIdx.x;
    int warp = t >> 5;
    int lane = t & 31;

    int b     = blockIdx.x;
    int half  = b & 1;                      // 0: floats [0,2048), 1: [2048,4096)
    long base = (long)(b >> 1) * TOKS;      // first token of this CTA
    // n_tokens = 16384 is a multiple of TOKS; all tokens valid.

    // packed offset for this thread within the row: half*1024 + t*8
    int poff = half * HALF_P + t * 8;
    int goff = poff >> 4;                   // scale group = half*64 + t/2

    float4* wbuf = buf + (size_t)warp * 2 * (SLICE_F / 4);

    // all 4 token indices in one load
    int4 idx4 = __ldg(reinterpret_cast<const int4*>(indices + base));
    int idxs[TOKS] = { idx4.x, idx4.y, idx4.z, idx4.w };

    // prefetch token 0
    const int4* wr = reinterpret_cast<const int4*>(weight + (long)idxs[0] * PACKED + poff);
    int4 w0 = __ldg(wr);
    int4 w1 = __ldg(wr + 1);
    float s = __ldg(scales + (long)idxs[0] * NGROUPS + goff);

    #pragma unroll
    for (int i = 0; i < TOKS; i++) {
        // prefetch token i+1 rows (index already in registers)
        int4 n0, n1; float ns;
        if (i + 1 < TOKS) {
            const int4* wr2 =
                reinterpret_cast<const int4*>(weight + (long)idxs[i + 1] * PACKED + poff);
            n0 = __ldg(wr2);
            n1 = __ldg(wr2 + 1);
            ns = __ldg(scales + (long)idxs[i + 1] * NGROUPS + goff);
        }

        // buffer (i&1) reuse guard: its bulk store was committed at iter i-2
        if (i >= 2 && lane == 0)
            asm volatile("cp.async.bulk.wait_group %0;" :: "n"(1) : "memory");
        __syncwarp();

        // dequant straight into smem (lane writes 4 consecutive float4 = 64B)
        float4* bp = wbuf + (size_t)(i & 1) * (SLICE_F / 4) + lane * 4;
        bp[0] = dq2(w0.x, w0.y, s);
        bp[1] = dq2(w0.z, w0.w, s);
        bp[2] = dq2(w1.x, w1.y, s);
        bp[3] = dq2(w1.z, w1.w, s);

        asm volatile("fence.proxy.async.shared::cta;" ::: "memory");
        __syncwarp();

        if (lane == 0) {
            uint32_t saddr = (uint32_t)__cvta_generic_to_shared(
                wbuf + (size_t)(i & 1) * (SLICE_F / 4));
            void* g = (void*)(out + (base + i) * DIM + half * HALF_F + warp * SLICE_F);
            asm volatile("cp.async.bulk.global.shared::cta.bulk_group [%0], [%1], %2;"
                         :: "l"(g), "r"(saddr), "n"(SLICE_B) : "memory");
            asm volatile("cp.async.bulk.commit_group;" ::: "memory");
        }

        w0 = n0; w1 = n1; s = ns;
    }

    if (lane == 0)
        asm volatile("cp.async.bulk.wait_group 0;" ::: "memory");
}

extern "C" void kernel_launch(void* const* d_in, const int* in_sizes, int n_in,
                              void* d_out, int out_size)
{
    const int*   indices = (const int*)d_in[0];
    const int*   weight  = (const int*)d_in[1];
    const float* scales  = (const float*)d_in[2];
    float*       out     = (float*)d_out;

    int n_tokens = in_sizes[0];  // 16384

    cudaFuncSetAttribute(qemb_kernel,
                         cudaFuncAttributeMaxDynamicSharedMemorySize, SMEM_BYTES);
    cudaFuncSetAttribute(qemb_kernel,
                         cudaFuncAttributePreferredSharedMemoryCarveout, 100);

    int grid = (n_tokens / TOKS) * 2;  // 8192 half-row CTAs
    qemb_kernel<<<grid, THREADS, SMEM_BYTES>>>(indices, weight, scales, out, n_tokens);
}

// round 9
// speedup vs baseline: 1.2298x; 1.0338x over previous
#include <cuda_runtime.h>
#include <cstdint>

// QuantizedEmbedding R9: full-TMA data path, warp-autonomous.
// Per warp per token: cp.async.bulk gather of its 1KB packed slice into smem
// (own mbarrier, double-buffered, issued 1 token ahead) -> LDS -> dequant ->
// STS -> cp.async.bulk store of its 2KB output slice (double-buffered,
// wait_group 1). No LDG on the weight stream; no CTA-wide barriers.

static constexpr int PACKED   = 2048;    // packed int32 per row (8KB)
static constexpr int NGROUPS  = 128;
static constexpr int DIM      = 4096;
static constexpr int THREADS  = 256;
static constexpr int WARPS    = THREADS / 32;          // 8
static constexpr int TOKS     = 4;                      // tokens per CTA
static constexpr int IN_P     = PACKED / WARPS;         // 256 int32 = 1KB per warp slice
static constexpr int IN_B     = IN_P * 4;               // 1024 B
static constexpr int SLICE_F  = DIM / WARPS;            // 512 floats = 2KB out slice
static constexpr int SLICE_B  = SLICE_F * 4;            // 2048 B
// smem: in bufs 8*2*1KB = 16KB, out bufs 8*2*2KB = 32KB, mbarriers 8*2*8B
static constexpr int SMEM_IN    = 0;
static constexpr int SMEM_OUT   = WARPS * 2 * IN_B;               // 16384
static constexpr int SMEM_MBAR  = SMEM_OUT + WARPS * 2 * SLICE_B; // 49152
static constexpr int SMEM_BYTES = SMEM_MBAR + WARPS * 2 * 8 + 64;

__device__ __forceinline__ float4 dq2(int a, int b, float s) {
    float4 r;
    r.x = (float)(a / 16 - 8) * s;       // trunc-toward-zero high nibble
    r.y = (float)((a & 15) - 8) * s;     // nonneg mod-16 low nibble
    r.z = (float)(b / 16 - 8) * s;
    r.w = (float)((b & 15) - 8) * s;
    return r;
}

__device__ __forceinline__ void mbar_wait(uint32_t mbar, uint32_t parity) {
    asm volatile(
        "{\n\t"
        ".reg .pred P;\n\t"
        "WL_%=:\n\t"
        "mbarrier.try_wait.parity.acquire.cta.shared::cta.b64 P, [%0], %1, 0x989680;\n\t"
        "@P bra.uni WD_%=;\n\t"
        "bra.uni WL_%=;\n\t"
        "WD_%=:\n\t"
        "}"
        :: "r"(mbar), "r"(parity) : "memory");
}

__global__ void __launch_bounds__(THREADS)
qemb_kernel(const int* __restrict__ indices,
            const int* __restrict__ weight,
            const float* __restrict__ scales,
            float* __restrict__ out,
            int n_tokens)
{
    extern __shared__ __align__(128) unsigned char smem[];
    uint32_t sbase = (uint32_t)__cvta_generic_to_shared(smem);

    int t    = threadIdx.x;
    int warp = t >> 5;
    int lane = t & 31;
    long base = (long)blockIdx.x * TOKS;   // 16384 tokens = 4096 CTAs * 4, exact

    // this warp's resources
    uint32_t in0  = sbase + SMEM_IN  + warp * 2 * IN_B;          // in bufs [2][1KB]
    uint32_t out0 = sbase + SMEM_OUT + warp * 2 * SLICE_B;       // out bufs [2][2KB]
    uint32_t mb0  = sbase + SMEM_MBAR + warp * 16;               // 2 mbarriers

    if (lane == 0) {
        asm volatile("mbarrier.init.shared.b64 [%0], 1;" :: "r"(mb0)     : "memory");
        asm volatile("mbarrier.init.shared.b64 [%0], 1;" :: "r"(mb0 + 8) : "memory");
        asm volatile("fence.proxy.async.shared::cta;" ::: "memory");
    }
    __syncwarp();

    // token indices for this CTA
    int4 idx4 = __ldg(reinterpret_cast<const int4*>(indices + base));
    int idxs[TOKS] = { idx4.x, idx4.y, idx4.z, idx4.w };

    // per-thread layout within warp slice:
    //   packed offset in row: warp*256 + lane*8   -> scale group warp*16 + lane/2
    int goff = warp * 16 + (lane >> 1);

    // prologue: issue bulk read of token 0 slice into in buf 0; prefetch scale 0
    if (lane == 0) {
        const int* src = weight + (long)idxs[0] * PACKED + warp * IN_P;
        asm volatile("mbarrier.arrive.expect_tx.shared.b64 _, [%0], %1;"
                     :: "r"(mb0), "n"(IN_B) : "memory");
        asm volatile("cp.async.bulk.shared::cta.global.mbarrier::complete_tx::bytes "
                     "[%0], [%1], %2, [%3];"
                     :: "r"(in0), "l"(src), "n"(IN_B), "r"(mb0) : "memory");
    }
    float s = __ldg(scales + (long)idxs[0] * NGROUPS + goff);

    #pragma unroll
    for (int i = 0; i < TOKS; i++) {
        int k = i & 1;

        // issue bulk read for token i+1 into buffer (i+1)&1 (consumed at iter i-1)
        float ns = s;
        if (i + 1 < TOKS) {
            if (lane == 0) {
                uint32_t mbn = mb0 + ((i + 1) & 1) * 8;
                uint32_t inn = in0 + ((i + 1) & 1) * IN_B;
                const int* src = weight + (long)idxs[i + 1] * PACKED + warp * IN_P;
                asm volatile("mbarrier.arrive.expect_tx.shared.b64 _, [%0], %1;"
                             :: "r"(mbn), "n"(IN_B) : "memory");
                asm volatile("cp.async.bulk.shared::cta.global.mbarrier::complete_tx::bytes "
                             "[%0], [%1], %2, [%3];"
                             :: "r"(inn), "l"(src), "n"(IN_B), "r"(mbn) : "memory");
            }
            ns = __ldg(scales + (long)idxs[i + 1] * NGROUPS + goff);
        }

        // wait for token i's slice: parity = (i>>1)&1
        mbar_wait(mb0 + k * 8, (i >> 1) & 1);

        // load 8 packed int32 (32B) from smem
        uint32_t a0 = in0 + k * IN_B + lane * 32;
        int4 w0, w1;
        asm volatile("ld.shared.v4.u32 {%0,%1,%2,%3}, [%4];"
                     : "=r"(w0.x), "=r"(w0.y), "=r"(w0.z), "=r"(w0.w) : "r"(a0));
        asm volatile("ld.shared.v4.u32 {%0,%1,%2,%3}, [%4];"
                     : "=r"(w1.x), "=r"(w1.y), "=r"(w1.z), "=r"(w1.w) : "r"(a0 + 16));

        // out buffer k reuse guard: its bulk store was committed at iter i-2
        if (i >= 2 && lane == 0)
            asm volatile("cp.async.bulk.wait_group %0;" :: "n"(1) : "memory");
        __syncwarp();

        // dequant into out buffer (lane writes 4 consecutive float4 = 64B)
        float4* bp = reinterpret_cast<float4*>(smem + SMEM_OUT
                       + warp * 2 * SLICE_B + k * SLICE_B) + lane * 4;
        bp[0] = dq2(w0.x, w0.y, s);
        bp[1] = dq2(w0.z, w0.w, s);
        bp[2] = dq2(w1.x, w1.y, s);
        bp[3] = dq2(w1.z, w1.w, s);

        asm volatile("fence.proxy.async.shared::cta;" ::: "memory");
        __syncwarp();

        if (lane == 0) {
            void* g = (void*)(out + (base + i) * DIM + warp * SLICE_F);
            asm volatile("cp.async.bulk.global.shared::cta.bulk_group [%0], [%1], %2;"
                         :: "l"(g), "r"(out0 + k * SLICE_B), "n"(SLICE_B) : "memory");
            asm volatile("cp.async.bulk.commit_group;" ::: "memory");
        }

        s = ns;
    }

    if (lane == 0)
        asm volatile("cp.async.bulk.wait_group 0;" ::: "memory");
}

extern "C" void kernel_launch(void* const* d_in, const int* in_sizes, int n_in,
                              void* d_out, int out_size)
{
    const int*   indices = (const int*)d_in[0];
    const int*   weight  = (const int*)d_in[1];
    const float* scales  = (const float*)d_in[2];
    float*       out     = (float*)d_out;

    int n_tokens = in_sizes[0];  // 16384

    cudaFuncSetAttribute(qemb_kernel,
                         cudaFuncAttributeMaxDynamicSharedMemorySize, SMEM_BYTES);
    cudaFuncSetAttribute(qemb_kernel,
                         cudaFuncAttributePreferredSharedMemoryCarveout, 100);

    int grid = n_tokens / TOKS;  // 4096
    qemb_kernel<<<grid, THREADS, SMEM_BYTES>>>(indices, weight, scales, out, n_tokens);
}